// round 16
// baseline (speedup 1.0000x reference)
#include <cuda_runtime.h>
#include <cstdint>
#include <math.h>

#define NEG_INF (__int_as_float(0xff800000))

// Problem constants
#define BB 4
#define SS 2048
#define EE 1024
#define AA 64

// 0.125 (1/sqrt(64)) * log2(e): carry logits in log2 domain so exp2f is a
// bare MUFU EX2.
#define SCALE_LOG2 0.18033688011112042f

typedef unsigned long long u64;
typedef unsigned int u32;

// packed f32x2 helpers (ptxas never auto-emits FFMA2 from C++)
__device__ __forceinline__ u64 fma2(u64 a, u64 b, u64 c) {
    u64 d;
    asm("fma.rn.f32x2 %0, %1, %2, %3;" : "=l"(d) : "l"(a), "l"(b), "l"(c));
    return d;
}
__device__ __forceinline__ float2 unpack2(u64 v) {
    float lo, hi;
    asm("mov.b64 {%0, %1}, %2;" : "=f"(lo), "=f"(hi) : "l"(v));
    return make_float2(lo, hi);
}
__device__ __forceinline__ float hsum2(u64 v) {
    float2 f = unpack2(v);
    return f.x + f.y;
}

// cp.async 16B (LDGSTS) helpers
__device__ __forceinline__ void cp_async16(u32 smem_addr, const void* gptr) {
    asm volatile("cp.async.cg.shared.global [%0], [%1], 16;"
                 :: "r"(smem_addr), "l"(gptr) : "memory");
}
__device__ __forceinline__ void cp_async_commit() {
    asm volatile("cp.async.commit_group;" ::: "memory");
}
__device__ __forceinline__ void cp_async_wait0() {
    asm volatile("cp.async.wait_group 0;" ::: "memory");
}
__device__ __forceinline__ u32 smem_u32(const void* p) {
    u32 a;
    asm("{ .reg .u64 t; cvta.to.shared.u64 t, %1; cvt.u32.u64 %0, t; }"
        : "=r"(a) : "l"(p));
    return a;
}

// Scratch: K = emb @ Wk^T  [B, S, A] fp32 = 2 MB
__device__ float g_K[BB * SS * AA];

// ---------------------------------------------------------------------------
// Kernel 1: K projection (R14 config: 128 CTAs x 64 rows, FFMA2 — the R15
// 256x32 split regressed; reverted).
// ---------------------------------------------------------------------------
__global__ __launch_bounds__(256, 2) void k_proj_kernel(
    const float* __restrict__ emb, const float* __restrict__ Wk)
{
    __shared__ float Es[64][68];
    __shared__ float Ws[64][68];

    const int t  = threadIdx.x;
    const int ty = t >> 4;
    const int tx = t & 15;
    const int rowbase = blockIdx.x * 64;

    u64 acc[4][4];
#pragma unroll
    for (int i = 0; i < 4; i++)
#pragma unroll
        for (int j = 0; j < 4; j++) acc[i][j] = 0ull;

    for (int et = 0; et < EE; et += 64) {
        __syncthreads();
#pragma unroll
        for (int g = 0; g < 4; g++) {
            int idx = t + g * 256;
            int r  = idx >> 4;
            int c4 = idx & 15;
            *(float4*)&Es[r][c4 * 4] =
                *(const float4*)&emb[(rowbase + r) * EE + et + c4 * 4];
            *(float4*)&Ws[r][c4 * 4] =
                *(const float4*)&Wk[r * EE + et + c4 * 4];
        }
        __syncthreads();

#pragma unroll
        for (int e4 = 0; e4 < 16; e4++) {
            ulonglong2 a0 = *(const ulonglong2*)&Es[ty      ][e4 * 4];
            ulonglong2 a1 = *(const ulonglong2*)&Es[ty + 16][e4 * 4];
            ulonglong2 a2 = *(const ulonglong2*)&Es[ty + 32][e4 * 4];
            ulonglong2 a3 = *(const ulonglong2*)&Es[ty + 48][e4 * 4];
#pragma unroll
            for (int j = 0; j < 4; j++) {
                ulonglong2 b = *(const ulonglong2*)&Ws[tx + 16 * j][e4 * 4];
                acc[0][j] = fma2(a0.x, b.x, acc[0][j]);
                acc[0][j] = fma2(a0.y, b.y, acc[0][j]);
                acc[1][j] = fma2(a1.x, b.x, acc[1][j]);
                acc[1][j] = fma2(a1.y, b.y, acc[1][j]);
                acc[2][j] = fma2(a2.x, b.x, acc[2][j]);
                acc[2][j] = fma2(a2.y, b.y, acc[2][j]);
                acc[3][j] = fma2(a3.x, b.x, acc[3][j]);
                acc[3][j] = fma2(a3.y, b.y, acc[3][j]);
            }
        }
    }

#pragma unroll
    for (int i = 0; i < 4; i++) {
        int row = rowbase + ty + 16 * i;
#pragma unroll
        for (int j = 0; j < 4; j++)
            g_K[row * AA + tx + 16 * j] = hsum2(acc[i][j]);
    }
}

// ---------------------------------------------------------------------------
// Kernel 2: causal flash attention, q = k = v = g_K.
// Exactly R14's structure (scalar PV, plain Ps staging — the R15 duplicated-P
// packing regressed and is reverted), plus two instruction-only cuts:
//  (a) logits in log2 domain -> exp2f = bare MUFU EX2 (no hidden multiply);
//  (b) row-sum l kept as per-lane partials, warp-reduced ONCE in the
//      epilogue (corr is warp-uniform so partials scale linearly);
//      removes 5 dependent shuffles x 4 rows per iteration.
// CTA = 128 threads, BQ=16, BK=128, 2 CTAs/SM, cp.async double buffering,
// one block barrier per iter, warp-local P staging.
// Dynamic smem: Qs[16][68] + 2*Ks[128][68] + Ps[16][132] = 82432 B.
// ---------------------------------------------------------------------------
#define QS_STRIDE 68
#define KS_STRIDE 68
#define PS_STRIDE 132
#define QS_OFF 0
#define KS0_OFF (16 * QS_STRIDE)                    // 1088
#define KS_TILE (128 * KS_STRIDE)                   // 8704
#define PS_OFF (KS0_OFF + 2 * KS_TILE)              // 18496
#define ATTN_SMEM_BYTES ((PS_OFF + 16 * PS_STRIDE) * 4)   // 82432

__global__ __launch_bounds__(128, 2) void attn_kernel(float* __restrict__ out)
{
    extern __shared__ float sm[];
    float* Qs = sm + QS_OFF;
    float* Ps = sm + PS_OFF;

    const int t  = threadIdx.x;
    const int ty = t >> 5;          // warp id 0..3
    const int tx = t & 31;          // lane
    const int dtx = tx & 15;        // PV dim group
    const int h   = tx >> 4;        // PV key-half selector
    const int bid = blockIdx.x;
    const int qt2 = 127 - (bid >> 2);   // heavy tiles first
    const int b   = bid & 3;
    const float* __restrict__ Kb = g_K + b * SS * AA;

    const int ktmax = (qt2 * 16 + 15) >> 7;     // inclusive, BK=128

    // per-thread cp.async slot: rows lr + 8g (g<16), column group lc4
    const int lr  = t >> 4;         // 0..7
    const int lc4 = t & 15;         // 16B column group

    // ---- prefetch K tile 0 into buffer 0 ----
    {
        u32 dst = smem_u32(sm + KS0_OFF) + (u32)((lr * KS_STRIDE + lc4 * 4) * 4);
        const float* src = Kb + lr * 64 + lc4 * 4;
#pragma unroll
        for (int g = 0; g < 16; g++)
            cp_async16(dst + g * 8 * KS_STRIDE * 4, src + g * 8 * 64);
        cp_async_commit();
    }

    // ---- load Q tile (16 x 64) ----
#pragma unroll
    for (int g = 0; g < 2; g++) {
        int idx = t + g * 128;
        int r  = idx >> 4;
        int c4 = idx & 15;
        *(float4*)&Qs[r * QS_STRIDE + c4 * 4] =
            *(const float4*)&Kb[(qt2 * 16 + r) * 64 + c4 * 4];
    }

    float4 o[4];
    float  m[4], l[4];
#pragma unroll
    for (int i = 0; i < 4; i++) {
        o[i] = make_float4(0.f, 0.f, 0.f, 0.f);
        m[i] = NEG_INF;
        l[i] = 0.f;                 // per-lane partial (reduced in epilogue)
    }
    const int rowg = qt2 * 16 + ty;             // + 4i per fragment row

    for (int kt = 0; kt <= ktmax; kt++) {
        float* Ks = sm + KS0_OFF + (kt & 1) * KS_TILE;

        cp_async_wait0();       // my copies for tile kt done
        __syncthreads();        // everyone's copies visible; prev compute done

        // ---- prefetch tile kt+1 into the other buffer ----
        if (kt < ktmax) {
            u32 dst = smem_u32(sm + KS0_OFF + ((kt + 1) & 1) * KS_TILE)
                    + (u32)((lr * KS_STRIDE + lc4 * 4) * 4);
            const float* src = Kb + ((kt + 1) * 128 + lr) * 64 + lc4 * 4;
#pragma unroll
            for (int g = 0; g < 16; g++)
                cp_async16(dst + g * 8 * KS_STRIDE * 4, src + g * 8 * 64);
            cp_async_commit();
        }

        // ---- scores: 4 rows x 4 keys, packed f32x2 along d ----
        u64 s2[4][4];
#pragma unroll
        for (int i = 0; i < 4; i++)
#pragma unroll
            for (int j = 0; j < 4; j++) s2[i][j] = 0ull;

#pragma unroll
        for (int d4 = 0; d4 < 16; d4++) {
            ulonglong2 q2[4], k2[4];
#pragma unroll
            for (int i = 0; i < 4; i++)
                q2[i] = *(const ulonglong2*)&Qs[(ty + 4 * i) * QS_STRIDE + d4 * 4];
#pragma unroll
            for (int j = 0; j < 4; j++)
                k2[j] = *(const ulonglong2*)&Ks[(tx + 32 * j) * KS_STRIDE + d4 * 4];
#pragma unroll
            for (int i = 0; i < 4; i++)
#pragma unroll
                for (int j = 0; j < 4; j++) {
                    s2[i][j] = fma2(q2[i].x, k2[j].x, s2[i][j]);
                    s2[i][j] = fma2(q2[i].y, k2[j].y, s2[i][j]);
                }
        }

        // ---- reduce pairs + log2-scale + faithful mask ----
        float s[4][4];
#pragma unroll
        for (int j = 0; j < 4; j++) {
            int gc = kt * 128 + tx + 32 * j;
#pragma unroll
            for (int i = 0; i < 4; i++) {
                float v = hsum2(s2[i][j]) * SCALE_LOG2;
                s[i][j] = (gc > rowg + 4 * i || v == 0.f) ? NEG_INF : v;
            }
        }

        // ---- online softmax (max warp-reduced; sum stays per-lane) ----
#pragma unroll
        for (int i = 0; i < 4; i++) {
            float tm = fmaxf(fmaxf(s[i][0], s[i][1]), fmaxf(s[i][2], s[i][3]));
            tm = fmaxf(tm, __shfl_xor_sync(0xffffffffu, tm, 16));
            tm = fmaxf(tm, __shfl_xor_sync(0xffffffffu, tm, 8));
            tm = fmaxf(tm, __shfl_xor_sync(0xffffffffu, tm, 4));
            tm = fmaxf(tm, __shfl_xor_sync(0xffffffffu, tm, 2));
            tm = fmaxf(tm, __shfl_xor_sync(0xffffffffu, tm, 1));
            float mn   = fmaxf(m[i], tm);
            float corr = (m[i] == mn) ? 1.f : exp2f(m[i] - mn);
            bool  dead = (mn == NEG_INF);
            float rs = 0.f;
#pragma unroll
            for (int j = 0; j < 4; j++) {
                float pv = dead ? 0.f : exp2f(s[i][j] - mn);
                s[i][j] = pv;
                rs += pv;
            }
            l[i] = l[i] * corr + rs;        // lane-local partial
            m[i] = mn;
            o[i].x *= corr; o[i].y *= corr; o[i].z *= corr; o[i].w *= corr;
        }

        // ---- stage P (warp-local: warp ty owns rows ty+4i) ----
#pragma unroll
        for (int i = 0; i < 4; i++)
#pragma unroll
            for (int j = 0; j < 4; j++)
                Ps[(ty + 4 * i) * PS_STRIDE + tx + 32 * j] = s[i][j];
        __syncwarp();

        // ---- O += P . V  (V tile == Ks), scalar FFMA, key-halves ----
#pragma unroll
        for (int c = 0; c < 16; c++) {
            int kb = c * 8 + h * 4;     // this lane's key chunk
            float4 p4[4];
#pragma unroll
            for (int i = 0; i < 4; i++)
                p4[i] = *(const float4*)&Ps[(ty + 4 * i) * PS_STRIDE + kb];
#pragma unroll
            for (int j = 0; j < 4; j++) {
                float4 v = *(const float4*)&Ks[(kb + j) * KS_STRIDE + dtx * 4];
                const float* pp[4] = {(const float*)&p4[0], (const float*)&p4[1],
                                      (const float*)&p4[2], (const float*)&p4[3]};
#pragma unroll
                for (int i = 0; i < 4; i++) {
                    float a = pp[i][j];
                    o[i].x += a * v.x; o[i].y += a * v.y;
                    o[i].z += a * v.z; o[i].w += a * v.w;
                }
            }
        }
    }

    // ---- epilogue ----
#pragma unroll
    for (int i = 0; i < 4; i++) {
        // reduce the per-lane row-sum partials once
        float rs = l[i];
        rs += __shfl_xor_sync(0xffffffffu, rs, 16);
        rs += __shfl_xor_sync(0xffffffffu, rs, 8);
        rs += __shfl_xor_sync(0xffffffffu, rs, 4);
        rs += __shfl_xor_sync(0xffffffffu, rs, 2);
        rs += __shfl_xor_sync(0xffffffffu, rs, 1);

        // merge key-halves (corr history warp-uniform => linear)
        o[i].x += __shfl_xor_sync(0xffffffffu, o[i].x, 16);
        o[i].y += __shfl_xor_sync(0xffffffffu, o[i].y, 16);
        o[i].z += __shfl_xor_sync(0xffffffffu, o[i].z, 16);
        o[i].w += __shfl_xor_sync(0xffffffffu, o[i].w, 16);

        if (h == 0) {
            float inv = 1.f / rs;
            float4 w = make_float4(o[i].x * inv, o[i].y * inv,
                                   o[i].z * inv, o[i].w * inv);
            int row = b * SS + qt2 * 16 + ty + 4 * i;
            *(float4*)&out[row * 64 + dtx * 4] = w;
        }
    }
}

// ---------------------------------------------------------------------------
extern "C" void kernel_launch(void* const* d_in, const int* in_sizes, int n_in,
                              void* d_out, int out_size)
{
    const float* emb = (const float*)d_in[0];   // [4, 2048, 1024]
    const float* Wk  = (const float*)d_in[1];   // [64, 1024]
    float* out = (float*)d_out;                 // [4, 2048, 64]
    (void)in_sizes; (void)n_in; (void)out_size;

    cudaFuncSetAttribute(attn_kernel,
                         cudaFuncAttributeMaxDynamicSharedMemorySize,
                         ATTN_SMEM_BYTES);

    k_proj_kernel<<<128, 256>>>(emb, Wk);
    attn_kernel<<<512, 128, ATTN_SMEM_BYTES>>>(out);
}

// round 17
// speedup vs baseline: 1.6308x; 1.6308x over previous
#include <cuda_runtime.h>
#include <cstdint>
#include <math.h>

#define NEG_INF (__int_as_float(0xff800000))

// Problem constants
#define BB 4
#define SS 2048
#define EE 1024
#define AA 64

// 0.125 (1/sqrt(64)) * log2(e): carry logits in log2 domain so the softmax
// exponential is a single MUFU EX2 (no hidden multiply).
#define SCALE_LOG2 0.18033688011112042f

typedef unsigned long long u64;
typedef unsigned int u32;

// packed f32x2 helpers (ptxas never auto-emits FFMA2 from C++)
__device__ __forceinline__ u64 fma2(u64 a, u64 b, u64 c) {
    u64 d;
    asm("fma.rn.f32x2 %0, %1, %2, %3;" : "=l"(d) : "l"(a), "l"(b), "l"(c));
    return d;
}
__device__ __forceinline__ float2 unpack2(u64 v) {
    float lo, hi;
    asm("mov.b64 {%0, %1}, %2;" : "=f"(lo), "=f"(hi) : "l"(v));
    return make_float2(lo, hi);
}
__device__ __forceinline__ float hsum2(u64 v) {
    float2 f = unpack2(v);
    return f.x + f.y;
}

// RAW MUFU EX2 — exp2f() without fast-math compiles to the slow accurate
// routine (R16 regression); this is the guaranteed single-instruction form.
__device__ __forceinline__ float ex2(float x) {
    float y;
    asm("ex2.approx.f32 %0, %1;" : "=f"(y) : "f"(x));
    return y;
}

// cp.async 16B (LDGSTS) helpers
__device__ __forceinline__ void cp_async16(u32 smem_addr, const void* gptr) {
    asm volatile("cp.async.cg.shared.global [%0], [%1], 16;"
                 :: "r"(smem_addr), "l"(gptr) : "memory");
}
__device__ __forceinline__ void cp_async_commit() {
    asm volatile("cp.async.commit_group;" ::: "memory");
}
__device__ __forceinline__ void cp_async_wait0() {
    asm volatile("cp.async.wait_group 0;" ::: "memory");
}
__device__ __forceinline__ u32 smem_u32(const void* p) {
    u32 a;
    asm("{ .reg .u64 t; cvta.to.shared.u64 t, %1; cvt.u32.u64 %0, t; }"
        : "=r"(a) : "l"(p));
    return a;
}

// Scratch: K = emb @ Wk^T  [B, S, A] fp32 = 2 MB
__device__ float g_K[BB * SS * AA];

// ---------------------------------------------------------------------------
// Kernel 1: K projection (R14 config: 128 CTAs x 64 rows, FFMA2).
// ---------------------------------------------------------------------------
__global__ __launch_bounds__(256, 2) void k_proj_kernel(
    const float* __restrict__ emb, const float* __restrict__ Wk)
{
    __shared__ float Es[64][68];
    __shared__ float Ws[64][68];

    const int t  = threadIdx.x;
    const int ty = t >> 4;
    const int tx = t & 15;
    const int rowbase = blockIdx.x * 64;

    u64 acc[4][4];
#pragma unroll
    for (int i = 0; i < 4; i++)
#pragma unroll
        for (int j = 0; j < 4; j++) acc[i][j] = 0ull;

    for (int et = 0; et < EE; et += 64) {
        __syncthreads();
#pragma unroll
        for (int g = 0; g < 4; g++) {
            int idx = t + g * 256;
            int r  = idx >> 4;
            int c4 = idx & 15;
            *(float4*)&Es[r][c4 * 4] =
                *(const float4*)&emb[(rowbase + r) * EE + et + c4 * 4];
            *(float4*)&Ws[r][c4 * 4] =
                *(const float4*)&Wk[r * EE + et + c4 * 4];
        }
        __syncthreads();

#pragma unroll
        for (int e4 = 0; e4 < 16; e4++) {
            ulonglong2 a0 = *(const ulonglong2*)&Es[ty      ][e4 * 4];
            ulonglong2 a1 = *(const ulonglong2*)&Es[ty + 16][e4 * 4];
            ulonglong2 a2 = *(const ulonglong2*)&Es[ty + 32][e4 * 4];
            ulonglong2 a3 = *(const ulonglong2*)&Es[ty + 48][e4 * 4];
#pragma unroll
            for (int j = 0; j < 4; j++) {
                ulonglong2 b = *(const ulonglong2*)&Ws[tx + 16 * j][e4 * 4];
                acc[0][j] = fma2(a0.x, b.x, acc[0][j]);
                acc[0][j] = fma2(a0.y, b.y, acc[0][j]);
                acc[1][j] = fma2(a1.x, b.x, acc[1][j]);
                acc[1][j] = fma2(a1.y, b.y, acc[1][j]);
                acc[2][j] = fma2(a2.x, b.x, acc[2][j]);
                acc[2][j] = fma2(a2.y, b.y, acc[2][j]);
                acc[3][j] = fma2(a3.x, b.x, acc[3][j]);
                acc[3][j] = fma2(a3.y, b.y, acc[3][j]);
            }
        }
    }

#pragma unroll
    for (int i = 0; i < 4; i++) {
        int row = rowbase + ty + 16 * i;
#pragma unroll
        for (int j = 0; j < 4; j++)
            g_K[row * AA + tx + 16 * j] = hsum2(acc[i][j]);
    }
}

// ---------------------------------------------------------------------------
// Kernel 2: causal flash attention, q = k = v = g_K.
// R14 structure (scalar PV, plain Ps staging, cp.async double buffering,
// one block barrier per iter, warp-local P staging) + two instruction cuts:
//  (a) log2-domain logits + RAW ex2.approx (single MUFU; exp2f() was the
//      R16 trap — slow accurate routine);
//  (b) row-sum l kept per-lane, warp-reduced once in the epilogue.
// Dynamic smem: Qs[16][68] + 2*Ks[128][68] + Ps[16][132] = 82432 B.
// ---------------------------------------------------------------------------
#define QS_STRIDE 68
#define KS_STRIDE 68
#define PS_STRIDE 132
#define QS_OFF 0
#define KS0_OFF (16 * QS_STRIDE)                    // 1088
#define KS_TILE (128 * KS_STRIDE)                   // 8704
#define PS_OFF (KS0_OFF + 2 * KS_TILE)              // 18496
#define ATTN_SMEM_BYTES ((PS_OFF + 16 * PS_STRIDE) * 4)   // 82432

__global__ __launch_bounds__(128, 2) void attn_kernel(float* __restrict__ out)
{
    extern __shared__ float sm[];
    float* Qs = sm + QS_OFF;
    float* Ps = sm + PS_OFF;

    const int t  = threadIdx.x;
    const int ty = t >> 5;          // warp id 0..3
    const int tx = t & 31;          // lane
    const int dtx = tx & 15;        // PV dim group
    const int h   = tx >> 4;        // PV key-half selector
    const int bid = blockIdx.x;
    const int qt2 = 127 - (bid >> 2);   // heavy tiles first
    const int b   = bid & 3;
    const float* __restrict__ Kb = g_K + b * SS * AA;

    const int ktmax = (qt2 * 16 + 15) >> 7;     // inclusive, BK=128

    // per-thread cp.async slot: rows lr + 8g (g<16), column group lc4
    const int lr  = t >> 4;         // 0..7
    const int lc4 = t & 15;         // 16B column group

    // ---- prefetch K tile 0 into buffer 0 ----
    {
        u32 dst = smem_u32(sm + KS0_OFF) + (u32)((lr * KS_STRIDE + lc4 * 4) * 4);
        const float* src = Kb + lr * 64 + lc4 * 4;
#pragma unroll
        for (int g = 0; g < 16; g++)
            cp_async16(dst + g * 8 * KS_STRIDE * 4, src + g * 8 * 64);
        cp_async_commit();
    }

    // ---- load Q tile (16 x 64) ----
#pragma unroll
    for (int g = 0; g < 2; g++) {
        int idx = t + g * 128;
        int r  = idx >> 4;
        int c4 = idx & 15;
        *(float4*)&Qs[r * QS_STRIDE + c4 * 4] =
            *(const float4*)&Kb[(qt2 * 16 + r) * 64 + c4 * 4];
    }

    float4 o[4];
    float  m[4], l[4];
#pragma unroll
    for (int i = 0; i < 4; i++) {
        o[i] = make_float4(0.f, 0.f, 0.f, 0.f);
        m[i] = NEG_INF;
        l[i] = 0.f;                 // per-lane partial (reduced in epilogue)
    }
    const int rowg = qt2 * 16 + ty;             // + 4i per fragment row

    for (int kt = 0; kt <= ktmax; kt++) {
        float* Ks = sm + KS0_OFF + (kt & 1) * KS_TILE;

        cp_async_wait0();       // my copies for tile kt done
        __syncthreads();        // everyone's copies visible; prev compute done

        // ---- prefetch tile kt+1 into the other buffer ----
        if (kt < ktmax) {
            u32 dst = smem_u32(sm + KS0_OFF + ((kt + 1) & 1) * KS_TILE)
                    + (u32)((lr * KS_STRIDE + lc4 * 4) * 4);
            const float* src = Kb + ((kt + 1) * 128 + lr) * 64 + lc4 * 4;
#pragma unroll
            for (int g = 0; g < 16; g++)
                cp_async16(dst + g * 8 * KS_STRIDE * 4, src + g * 8 * 64);
            cp_async_commit();
        }

        // ---- scores: 4 rows x 4 keys, packed f32x2 along d ----
        u64 s2[4][4];
#pragma unroll
        for (int i = 0; i < 4; i++)
#pragma unroll
            for (int j = 0; j < 4; j++) s2[i][j] = 0ull;

#pragma unroll
        for (int d4 = 0; d4 < 16; d4++) {
            ulonglong2 q2[4], k2[4];
#pragma unroll
            for (int i = 0; i < 4; i++)
                q2[i] = *(const ulonglong2*)&Qs[(ty + 4 * i) * QS_STRIDE + d4 * 4];
#pragma unroll
            for (int j = 0; j < 4; j++)
                k2[j] = *(const ulonglong2*)&Ks[(tx + 32 * j) * KS_STRIDE + d4 * 4];
#pragma unroll
            for (int i = 0; i < 4; i++)
#pragma unroll
                for (int j = 0; j < 4; j++) {
                    s2[i][j] = fma2(q2[i].x, k2[j].x, s2[i][j]);
                    s2[i][j] = fma2(q2[i].y, k2[j].y, s2[i][j]);
                }
        }

        // ---- reduce pairs + log2-scale + faithful mask ----
        float s[4][4];
#pragma unroll
        for (int j = 0; j < 4; j++) {
            int gc = kt * 128 + tx + 32 * j;
#pragma unroll
            for (int i = 0; i < 4; i++) {
                float v = hsum2(s2[i][j]) * SCALE_LOG2;
                s[i][j] = (gc > rowg + 4 * i || v == 0.f) ? NEG_INF : v;
            }
        }

        // ---- online softmax (max warp-reduced; sum stays per-lane) ----
#pragma unroll
        for (int i = 0; i < 4; i++) {
            float tm = fmaxf(fmaxf(s[i][0], s[i][1]), fmaxf(s[i][2], s[i][3]));
            tm = fmaxf(tm, __shfl_xor_sync(0xffffffffu, tm, 16));
            tm = fmaxf(tm, __shfl_xor_sync(0xffffffffu, tm, 8));
            tm = fmaxf(tm, __shfl_xor_sync(0xffffffffu, tm, 4));
            tm = fmaxf(tm, __shfl_xor_sync(0xffffffffu, tm, 2));
            tm = fmaxf(tm, __shfl_xor_sync(0xffffffffu, tm, 1));
            float mn   = fmaxf(m[i], tm);
            float corr = (m[i] == mn) ? 1.f : ex2(m[i] - mn);
            bool  dead = (mn == NEG_INF);
            float rs = 0.f;
#pragma unroll
            for (int j = 0; j < 4; j++) {
                float pv = dead ? 0.f : ex2(s[i][j] - mn);
                s[i][j] = pv;
                rs += pv;
            }
            l[i] = l[i] * corr + rs;        // lane-local partial
            m[i] = mn;
            o[i].x *= corr; o[i].y *= corr; o[i].z *= corr; o[i].w *= corr;
        }

        // ---- stage P (warp-local: warp ty owns rows ty+4i) ----
#pragma unroll
        for (int i = 0; i < 4; i++)
#pragma unroll
            for (int j = 0; j < 4; j++)
                Ps[(ty + 4 * i) * PS_STRIDE + tx + 32 * j] = s[i][j];
        __syncwarp();

        // ---- O += P . V  (V tile == Ks), scalar FFMA, key-halves ----
#pragma unroll
        for (int c = 0; c < 16; c++) {
            int kb = c * 8 + h * 4;     // this lane's key chunk
            float4 p4[4];
#pragma unroll
            for (int i = 0; i < 4; i++)
                p4[i] = *(const float4*)&Ps[(ty + 4 * i) * PS_STRIDE + kb];
#pragma unroll
            for (int j = 0; j < 4; j++) {
                float4 v = *(const float4*)&Ks[(kb + j) * KS_STRIDE + dtx * 4];
                const float* pp[4] = {(const float*)&p4[0], (const float*)&p4[1],
                                      (const float*)&p4[2], (const float*)&p4[3]};
#pragma unroll
                for (int i = 0; i < 4; i++) {
                    float a = pp[i][j];
                    o[i].x += a * v.x; o[i].y += a * v.y;
                    o[i].z += a * v.z; o[i].w += a * v.w;
                }
            }
        }
    }

    // ---- epilogue ----
#pragma unroll
    for (int i = 0; i < 4; i++) {
        // reduce the per-lane row-sum partials once
        float rs = l[i];
        rs += __shfl_xor_sync(0xffffffffu, rs, 16);
        rs += __shfl_xor_sync(0xffffffffu, rs, 8);
        rs += __shfl_xor_sync(0xffffffffu, rs, 4);
        rs += __shfl_xor_sync(0xffffffffu, rs, 2);
        rs += __shfl_xor_sync(0xffffffffu, rs, 1);

        // merge key-halves (corr history warp-uniform => linear)
        o[i].x += __shfl_xor_sync(0xffffffffu, o[i].x, 16);
        o[i].y += __shfl_xor_sync(0xffffffffu, o[i].y, 16);
        o[i].z += __shfl_xor_sync(0xffffffffu, o[i].z, 16);
        o[i].w += __shfl_xor_sync(0xffffffffu, o[i].w, 16);

        if (h == 0) {
            float inv = 1.f / rs;
            float4 w = make_float4(o[i].x * inv, o[i].y * inv,
                                   o[i].z * inv, o[i].w * inv);
            int row = b * SS + qt2 * 16 + ty + 4 * i;
            *(float4*)&out[row * 64 + dtx * 4] = w;
        }
    }
}

// ---------------------------------------------------------------------------
extern "C" void kernel_launch(void* const* d_in, const int* in_sizes, int n_in,
                              void* d_out, int out_size)
{
    const float* emb = (const float*)d_in[0];   // [4, 2048, 1024]
    const float* Wk  = (const float*)d_in[1];   // [64, 1024]
    float* out = (float*)d_out;                 // [4, 2048, 64]
    (void)in_sizes; (void)n_in; (void)out_size;

    cudaFuncSetAttribute(attn_kernel,
                         cudaFuncAttributeMaxDynamicSharedMemorySize,
                         ATTN_SMEM_BYTES);

    k_proj_kernel<<<128, 256>>>(emb, Wk);
    attn_kernel<<<512, 128, ATTN_SMEM_BYTES>>>(out);
}